// round 1
// baseline (speedup 1.0000x reference)
#include <cuda_runtime.h>
#include <cstdint>

// y = x @ W^T,  W[o,k] = scales[o, k/32] * (codes[o,k] - 128)
// x: [2,2048,4096] f32  -> M=4096, K=4096
// scales: [4096,128] f32, codes: [4096,128,32] int32 -> N=4096
// out: [2,2048,4096] f32
//
// Fused-dequant TF32 tensor-core GEMM, CTA tile 128x128x32.

#define IN_DIM   4096
#define OUT_DIM  4096
#define NBLK_    128
#define BM       128
#define BN       128
#define BK       32
#define THREADS  256
#define SSTRIDE  36   // BK + 4 pad: frag LDS bank = (36*r + c) % 32 = (4r + c) -> conflict-free

__device__ __forceinline__ uint32_t f2tf32(float f) {
    uint32_t r;
    asm("cvt.rna.tf32.f32 %0, %1;" : "=r"(r) : "f"(f));
    return r;
}

__device__ __forceinline__ void mma_tf32(float* c,
                                         uint32_t a0, uint32_t a1, uint32_t a2, uint32_t a3,
                                         uint32_t b0, uint32_t b1) {
    asm volatile(
        "mma.sync.aligned.m16n8k8.row.col.f32.tf32.tf32.f32 "
        "{%0,%1,%2,%3}, {%4,%5,%6,%7}, {%8,%9}, {%0,%1,%2,%3};"
        : "+f"(c[0]), "+f"(c[1]), "+f"(c[2]), "+f"(c[3])
        : "r"(a0), "r"(a1), "r"(a2), "r"(a3), "r"(b0), "r"(b1));
}

__global__ __launch_bounds__(THREADS)
void gguf_tf32_gemm(const float* __restrict__ x,
                    const float* __restrict__ scales,
                    const int*   __restrict__ codes,
                    float* __restrict__ y)
{
    __shared__ uint32_t As[BM * SSTRIDE];   // A tile, tf32 bits, [m][k]
    __shared__ uint32_t Bs[BN * SSTRIDE];   // W tile, tf32 bits, [n][k]

    const int tid  = threadIdx.x;
    const int lane = tid & 31;
    const int wid  = tid >> 5;
    const int wm   = wid >> 1;   // 0..3 : warp row (32 m each)
    const int wn   = wid & 1;    // 0..1 : warp col (64 n each)

    const int m0 = blockIdx.y * BM;
    const int n0 = blockIdx.x * BN;

    float acc[2][8][4];
    #pragma unroll
    for (int i = 0; i < 2; i++)
        #pragma unroll
        for (int j = 0; j < 8; j++)
            #pragma unroll
            for (int v = 0; v < 4; v++) acc[i][j][v] = 0.0f;

    const int lrow_q = lane >> 2;   // 0..7
    const int lcol_q = lane & 3;    // 0..3

    for (int kb = 0; kb < NBLK_; kb++) {
        const int kbase = kb * BK;

        // ---- load A tile: 128x32 f32 = 1024 float4, 4 per thread ----
        #pragma unroll
        for (int it = 0; it < 4; it++) {
            int idx = tid + it * THREADS;      // 0..1023
            int row = idx >> 3;                // 0..127
            int c4  = idx & 7;                 // 0..7
            float4 v = *reinterpret_cast<const float4*>(
                x + (size_t)(m0 + row) * IN_DIM + kbase + c4 * 4);
            uint4 t;
            t.x = f2tf32(v.x); t.y = f2tf32(v.y);
            t.z = f2tf32(v.z); t.w = f2tf32(v.w);
            *reinterpret_cast<uint4*>(&As[row * SSTRIDE + c4 * 4]) = t;
        }

        // ---- load + dequant B tile: 128 rows x 32 codes ----
        #pragma unroll
        for (int it = 0; it < 4; it++) {
            int idx = tid + it * THREADS;
            int row = idx >> 3;
            int c4  = idx & 7;
            int n   = n0 + row;
            int4 cv = *reinterpret_cast<const int4*>(
                codes + (size_t)n * IN_DIM + kbase + c4 * 4);
            float s = scales[(size_t)n * NBLK_ + kb];
            uint4 t;
            t.x = f2tf32(s * (float)(cv.x - 128));
            t.y = f2tf32(s * (float)(cv.y - 128));
            t.z = f2tf32(s * (float)(cv.z - 128));
            t.w = f2tf32(s * (float)(cv.w - 128));
            *reinterpret_cast<uint4*>(&Bs[row * SSTRIDE + c4 * 4]) = t;
        }

        __syncthreads();

        // ---- compute: 4 k-steps of 8, warp tile 32x64 = 2x8 mma tiles ----
        #pragma unroll
        for (int ks = 0; ks < BK; ks += 8) {
            uint32_t afr[2][4];
            const int ar0 = wm * 32 + lrow_q;
            const int ac  = ks + lcol_q;
            #pragma unroll
            for (int mt = 0; mt < 2; mt++) {
                int r = ar0 + mt * 16;
                afr[mt][0] = As[(r    ) * SSTRIDE + ac    ];
                afr[mt][1] = As[(r + 8) * SSTRIDE + ac    ];
                afr[mt][2] = As[(r    ) * SSTRIDE + ac + 4];
                afr[mt][3] = As[(r + 8) * SSTRIDE + ac + 4];
            }
            uint32_t bfr[8][2];
            const int br0 = wn * 64 + lrow_q;
            #pragma unroll
            for (int nt = 0; nt < 8; nt++) {
                int b = br0 + nt * 8;
                bfr[nt][0] = Bs[b * SSTRIDE + ks + lcol_q    ];
                bfr[nt][1] = Bs[b * SSTRIDE + ks + lcol_q + 4];
            }
            #pragma unroll
            for (int mt = 0; mt < 2; mt++)
                #pragma unroll
                for (int nt = 0; nt < 8; nt++)
                    mma_tf32(acc[mt][nt],
                             afr[mt][0], afr[mt][1], afr[mt][2], afr[mt][3],
                             bfr[nt][0], bfr[nt][1]);
        }

        __syncthreads();
    }

    // ---- epilogue: c0,c1 at (row, 2c), (row, 2c+1); c2,c3 at row+8 ----
    const int mrow  = m0 + wm * 32 + lrow_q;
    const int ncol0 = n0 + wn * 64 + lcol_q * 2;
    #pragma unroll
    for (int mt = 0; mt < 2; mt++) {
        #pragma unroll
        for (int nt = 0; nt < 8; nt++) {
            int r = mrow + mt * 16;
            int c = ncol0 + nt * 8;
            float2 lo = make_float2(acc[mt][nt][0], acc[mt][nt][1]);
            float2 hi = make_float2(acc[mt][nt][2], acc[mt][nt][3]);
            *reinterpret_cast<float2*>(y + (size_t)r * OUT_DIM + c)       = lo;
            *reinterpret_cast<float2*>(y + (size_t)(r + 8) * OUT_DIM + c) = hi;
        }
    }
}

extern "C" void kernel_launch(void* const* d_in, const int* in_sizes, int n_in,
                              void* d_out, int out_size) {
    const float* x      = (const float*)d_in[0];
    const float* scales = (const float*)d_in[1];
    const int*   codes  = (const int*)d_in[2];
    float*       y      = (float*)d_out;

    int M = in_sizes[0] / IN_DIM;          // 2*2048 = 4096
    dim3 grid(OUT_DIM / BN, M / BM);       // (32, 32)
    gguf_tf32_gemm<<<grid, THREADS>>>(x, scales, codes, y);
}

// round 2
// speedup vs baseline: 3.8534x; 3.8534x over previous
#include <cuda_runtime.h>
#include <cuda_fp16.h>
#include <cstdint>

// y = x @ W^T,  W[o,k] = scales[o,k/32] * (codes[o,k] - 128)
// Strategy: pre-pass converts x (f32->f16) and dequantizes W (->f16) into
// __device__ scratch; main GEMM is fp16 HMMA m16n8k16 with cp.async 3-stage
// pipeline, XOR-swizzled smem, ldmatrix fragment loads, f32 accumulate.

#define IN_DIM   4096
#define OUT_DIM  4096
#define M_DIM    4096
#define NBLK_    128
#define BM       128
#define BN       128
#define BK       64
#define STAGES   3
#define THREADS  256
#define KITERS   (IN_DIM / BK)   // 64

// 32 MB each — static device scratch (allowed; no runtime alloc)
__device__ __half g_xh[(size_t)M_DIM * IN_DIM];
__device__ __half g_wh[(size_t)OUT_DIM * IN_DIM];

// smem halves: A stages [0, 3*8192), B stages [24576, 49152)
#define A_STAGE_H   (BM * BK)            // 8192
#define B_BASE_H    (STAGES * A_STAGE_H) // 24576
#define SMEM_HALVES (2 * STAGES * A_STAGE_H)
#define SMEM_BYTES  (SMEM_HALVES * 2)    // 98304

// ---------------- pre-pass kernels ----------------

__global__ void cvt_x_kernel(const float4* __restrict__ x) {
    int i = blockIdx.x * blockDim.x + threadIdx.x;   // one float4 each
    if (i >= (M_DIM * IN_DIM) / 4) return;
    float4 v = x[i];
    __half2 h0 = __floats2half2_rn(v.x, v.y);
    __half2 h1 = __floats2half2_rn(v.z, v.w);
    uint2 u;
    u.x = *reinterpret_cast<uint32_t*>(&h0);
    u.y = *reinterpret_cast<uint32_t*>(&h1);
    reinterpret_cast<uint2*>(g_xh)[i] = u;
}

__global__ void dequant_kernel(const float* __restrict__ scales,
                               const int4* __restrict__ codes) {
    int i = blockIdx.x * blockDim.x + threadIdx.x;   // one int4 (4 codes) each
    if (i >= (OUT_DIM * IN_DIM) / 4) return;
    int gelt = i * 4;
    int o  = gelt >> 12;          // / 4096
    int kb = (gelt & 4095) >> 5;  // block index
    float s = __ldg(scales + o * NBLK_ + kb);
    int4 c = codes[i];
    __half2 h0 = __floats2half2_rn(s * (float)(c.x - 128), s * (float)(c.y - 128));
    __half2 h1 = __floats2half2_rn(s * (float)(c.z - 128), s * (float)(c.w - 128));
    uint2 u;
    u.x = *reinterpret_cast<uint32_t*>(&h0);
    u.y = *reinterpret_cast<uint32_t*>(&h1);
    reinterpret_cast<uint2*>(g_wh)[i] = u;
}

// ---------------- GEMM ----------------

__device__ __forceinline__ void cp_async16(uint32_t saddr, const void* g) {
    asm volatile("cp.async.cg.shared.global [%0], [%1], 16;" :: "r"(saddr), "l"(g));
}
__device__ __forceinline__ void cp_commit() {
    asm volatile("cp.async.commit_group;");
}
template <int N>
__device__ __forceinline__ void cp_wait() {
    asm volatile("cp.async.wait_group %0;" :: "n"(N));
}
__device__ __forceinline__ void ldsm_x4(uint32_t& r0, uint32_t& r1,
                                        uint32_t& r2, uint32_t& r3, uint32_t addr) {
    asm volatile("ldmatrix.sync.aligned.m8n8.x4.shared.b16 {%0,%1,%2,%3}, [%4];"
                 : "=r"(r0), "=r"(r1), "=r"(r2), "=r"(r3) : "r"(addr));
}
__device__ __forceinline__ void mma_f16(float* c, const uint32_t* a, const uint32_t* b) {
    asm volatile(
        "mma.sync.aligned.m16n8k16.row.col.f32.f16.f16.f32 "
        "{%0,%1,%2,%3}, {%4,%5,%6,%7}, {%8,%9}, {%0,%1,%2,%3};"
        : "+f"(c[0]), "+f"(c[1]), "+f"(c[2]), "+f"(c[3])
        : "r"(a[0]), "r"(a[1]), "r"(a[2]), "r"(a[3]), "r"(b[0]), "r"(b[1]));
}

// swizzled half-offset within a 128x64 tile: row-major, chunk = 8 halves (16B),
// physical chunk = logical chunk ^ (row & 7)  -> conflict-free LDSM & cp.async
__device__ __forceinline__ int tile_off(int row, int chunk) {
    return row * BK + ((chunk ^ (row & 7)) << 3);
}

__device__ __forceinline__ void load_stage(int kb, int st, int m0, int n0,
                                           int tid, uint32_t smem_u32) {
    const __half* gA = g_xh + (size_t)m0 * IN_DIM + kb * BK;
    const __half* gB = g_wh + (size_t)n0 * IN_DIM + kb * BK;
    #pragma unroll
    for (int it = 0; it < 4; it++) {
        int idx = tid + it * THREADS;   // 0..1023
        int row = idx >> 3;             // 0..127
        int c   = idx & 7;              // 0..7
        uint32_t sA = smem_u32 + (uint32_t)(st * A_STAGE_H + tile_off(row, c)) * 2;
        uint32_t sB = smem_u32 + (uint32_t)(B_BASE_H + st * A_STAGE_H + tile_off(row, c)) * 2;
        cp_async16(sA, gA + (size_t)row * IN_DIM + c * 8);
        cp_async16(sB, gB + (size_t)row * IN_DIM + c * 8);
    }
}

__global__ __launch_bounds__(THREADS)
void gguf_hgemm(float* __restrict__ y) {
    extern __shared__ __half sm[];
    uint32_t smem_u32 = (uint32_t)__cvta_generic_to_shared(sm);

    const int tid  = threadIdx.x;
    const int lane = tid & 31;
    const int wid  = tid >> 5;
    const int wm   = wid >> 1;     // 0..3 -> 32 m rows each
    const int wn   = wid & 1;      // 0..1 -> 64 n cols each

    const int m0 = blockIdx.y * BM;
    const int n0 = blockIdx.x * BN;

    float acc[2][8][4];
    #pragma unroll
    for (int i = 0; i < 2; i++)
        #pragma unroll
        for (int j = 0; j < 8; j++)
            #pragma unroll
            for (int v = 0; v < 4; v++) acc[i][j][v] = 0.0f;

    // ldmatrix per-lane geometry
    const int a_lr = lane & 15;                       // row within 16-block
    const int a_lc = lane >> 4;                       // 0/1 -> +8 k chunk
    const int b_lr = (lane & 7) + ((lane >> 4) << 3); // row within 16-n pair
    const int b_lc = (lane >> 3) & 1;                 // 0/1 -> +8 k chunk

    int rowA[2], rowB[4];
    #pragma unroll
    for (int mt = 0; mt < 2; mt++) rowA[mt] = wm * 32 + mt * 16 + a_lr;
    #pragma unroll
    for (int p = 0; p < 4; p++)    rowB[p]  = wn * 64 + p * 16 + b_lr;

    // prologue: stages 0,1 in flight
    load_stage(0, 0, m0, n0, tid, smem_u32); cp_commit();
    load_stage(1, 1, m0, n0, tid, smem_u32); cp_commit();
    cp_wait<1>();
    __syncthreads();

    int st = 0;
    for (int kb = 0; kb < KITERS; kb++) {
        int nxt = kb + 2;
        if (nxt < KITERS) {
            load_stage(nxt, nxt % STAGES, m0, n0, tid, smem_u32);
        }
        cp_commit();

        const uint32_t aBase = smem_u32 + (uint32_t)(st * A_STAGE_H) * 2;
        const uint32_t bBase = smem_u32 + (uint32_t)(B_BASE_H + st * A_STAGE_H) * 2;

        #pragma unroll
        for (int ks = 0; ks < BK / 16; ks++) {        // 4 k-steps of 16
            const int ck0 = ks * 2;
            uint32_t afr[2][4];
            #pragma unroll
            for (int mt = 0; mt < 2; mt++) {
                int r = rowA[mt];
                uint32_t addr = aBase + (uint32_t)(r * BK + (((ck0 + a_lc) ^ (r & 7)) << 3)) * 2;
                ldsm_x4(afr[mt][0], afr[mt][1], afr[mt][2], afr[mt][3], addr);
            }
            uint32_t bfr[8][2];
            #pragma unroll
            for (int p = 0; p < 4; p++) {
                int r = rowB[p];
                uint32_t addr = bBase + (uint32_t)(r * BK + (((ck0 + b_lc) ^ (r & 7)) << 3)) * 2;
                uint32_t r0, r1, r2, r3;
                ldsm_x4(r0, r1, r2, r3, addr);
                bfr[2 * p][0] = r0; bfr[2 * p][1] = r1;
                bfr[2 * p + 1][0] = r2; bfr[2 * p + 1][1] = r3;
            }
            #pragma unroll
            for (int mt = 0; mt < 2; mt++)
                #pragma unroll
                for (int nt = 0; nt < 8; nt++)
                    mma_f16(acc[mt][nt], afr[mt], bfr[nt]);
        }

        cp_wait<1>();
        __syncthreads();
        st = (st + 1) % STAGES;
    }

    // epilogue
    const int lrow_q = lane >> 2;
    const int lcol_q = lane & 3;
    const int mrow  = m0 + wm * 32 + lrow_q;
    const int ncol0 = n0 + wn * 64 + lcol_q * 2;
    #pragma unroll
    for (int mt = 0; mt < 2; mt++) {
        #pragma unroll
        for (int nt = 0; nt < 8; nt++) {
            int r = mrow + mt * 16;
            int c = ncol0 + nt * 8;
            float2 lo = make_float2(acc[mt][nt][0], acc[mt][nt][1]);
            float2 hi = make_float2(acc[mt][nt][2], acc[mt][nt][3]);
            *reinterpret_cast<float2*>(y + (size_t)r * OUT_DIM + c)       = lo;
            *reinterpret_cast<float2*>(y + (size_t)(r + 8) * OUT_DIM + c) = hi;
        }
    }
}

extern "C" void kernel_launch(void* const* d_in, const int* in_sizes, int n_in,
                              void* d_out, int out_size) {
    const float* x      = (const float*)d_in[0];
    const float* scales = (const float*)d_in[1];
    const int*   codes  = (const int*)d_in[2];
    float*       y      = (float*)d_out;

    cudaFuncSetAttribute(gguf_hgemm, cudaFuncAttributeMaxDynamicSharedMemorySize, SMEM_BYTES);

    int nx4 = (M_DIM * IN_DIM) / 4;
    cvt_x_kernel<<<(nx4 + 255) / 256, 256>>>(reinterpret_cast<const float4*>(x));

    int nw4 = (OUT_DIM * IN_DIM) / 4;
    dequant_kernel<<<(nw4 + 255) / 256, 256>>>(scales, reinterpret_cast<const int4*>(codes));

    dim3 grid(OUT_DIM / BN, M_DIM / BM);   // (32, 32)
    gguf_hgemm<<<grid, THREADS, SMEM_BYTES>>>(y);
}